// round 3
// baseline (speedup 1.0000x reference)
#include <cuda_runtime.h>
#include <cuda_fp16.h>
#include <cstdint>

// Problem dims (fixed by the dataset)
constexpr int M_DIM = 8192;    // B*S = 4*2048
constexpr int N_DIM = 11008;   // OUT_F
constexpr int K_DIM = 4096;    // IN_F

constexpr int BM = 128;
constexpr int BN = 128;
constexpr int BK = 32;
constexpr int KT = K_DIM / BK;   // 128
constexpr int PAD = 8;           // row stride 40 halves = 80B -> conflict-free ldmatrix

__device__ __forceinline__ uint32_t pack_f2(float a, float b) {
    __half2 h = __floats2half2_rn(a, b);
    return *reinterpret_cast<uint32_t*>(&h);
}
__device__ __forceinline__ uint32_t pack_i2(int a, int b) {
    __half2 h = __halves2half2(__short2half_rn((short)a), __short2half_rn((short)b));
    return *reinterpret_cast<uint32_t*>(&h);
}

__global__ __launch_bounds__(256, 2)
void w8_gemm_kernel(const float* __restrict__ x,
                    const int*   __restrict__ qw,     // int8 values stored as int32
                    const float* __restrict__ scale,
                    const float* __restrict__ bias,
                    float* __restrict__ out)
{
    __shared__ __align__(16) __half As[2][BM][BK + PAD];
    __shared__ __align__(16) __half Bs[2][BN][BK + PAD];

    const int tid  = threadIdx.x;
    const int lane = tid & 31;
    const int wid  = tid >> 5;
    const int wm   = wid >> 2;   // 0..1 : warp row (64 M each)
    const int wn   = wid & 3;    // 0..3 : warp col (32 N each)

    const int m_base = blockIdx.y * BM;
    const int n_base = blockIdx.x * BN;

    // ---- global staging addresses ----
    // A (f32): 128 rows x 32 floats per tile; thread loads 8 floats x 2 row groups
    const int arow = tid >> 2;            // 0..63 (and +64)
    const int acol = (tid & 3) * 8;       // 0,8,16,24 (floats)
    const float* aptr = x + (size_t)(m_base + arow) * K_DIM + acol;
    // B (int32): 128 rows x 32 ints; thread loads 16 ints (4x int4)
    const int brow = tid >> 1;            // 0..127
    const int bcol = (tid & 1) * 16;      // 0,16 (int32 elements)
    const int* bptr = qw + (size_t)(n_base + brow) * K_DIM + bcol;

    float acc[4][4][4];
    #pragma unroll
    for (int i = 0; i < 4; i++)
        #pragma unroll
        for (int j = 0; j < 4; j++)
            #pragma unroll
            for (int l = 0; l < 4; l++) acc[i][j][l] = 0.f;

    float4 a00, a01, a10, a11;   // A staging: two row groups x 8 floats
    int4   b0, b1, b2, b3;       // B staging: 16 int32

    auto load_gmem = [&](int kt) {
        const float* ap = aptr + (size_t)kt * BK;
        a00 = *(const float4*)(ap);
        a01 = *(const float4*)(ap + 4);
        a10 = *(const float4*)(ap + (size_t)64 * K_DIM);
        a11 = *(const float4*)(ap + (size_t)64 * K_DIM + 4);
        const int* bp = bptr + kt * BK;
        b0 = *(const int4*)(bp);
        b1 = *(const int4*)(bp + 4);
        b2 = *(const int4*)(bp + 8);
        b3 = *(const int4*)(bp + 12);
    };

    auto store_tile = [&](int buf) {
        // f32 -> fp16 (lossless: values originate from fp16)
        uint4 v0, v1;
        v0.x = pack_f2(a00.x, a00.y); v0.y = pack_f2(a00.z, a00.w);
        v0.z = pack_f2(a01.x, a01.y); v0.w = pack_f2(a01.z, a01.w);
        v1.x = pack_f2(a10.x, a10.y); v1.y = pack_f2(a10.z, a10.w);
        v1.z = pack_f2(a11.x, a11.y); v1.w = pack_f2(a11.z, a11.w);
        *(uint4*)&As[buf][arow][acol]      = v0;
        *(uint4*)&As[buf][arow + 64][acol] = v1;
        // int32 -> fp16 dequant during staging
        uint4 w0, w1;
        w0.x = pack_i2(b0.x, b0.y); w0.y = pack_i2(b0.z, b0.w);
        w0.z = pack_i2(b1.x, b1.y); w0.w = pack_i2(b1.z, b1.w);
        w1.x = pack_i2(b2.x, b2.y); w1.y = pack_i2(b2.z, b2.w);
        w1.z = pack_i2(b3.x, b3.y); w1.w = pack_i2(b3.z, b3.w);
        *(uint4*)&Bs[buf][brow][bcol]     = w0;
        *(uint4*)&Bs[buf][brow][bcol + 8] = w1;
    };

    auto compute = [&](int buf) {
        #pragma unroll
        for (int kk = 0; kk < 2; kk++) {   // two k16 steps per BK=32
            uint32_t Af[4][4];
            #pragma unroll
            for (int mi = 0; mi < 4; mi++) {
                const __half* p = &As[buf][wm * 64 + mi * 16 + (lane & 15)]
                                        [kk * 16 + (lane >> 4) * 8];
                uint32_t addr = (uint32_t)__cvta_generic_to_shared(p);
                asm volatile(
                    "ldmatrix.sync.aligned.m8n8.x4.shared.b16 {%0,%1,%2,%3}, [%4];"
                    : "=r"(Af[mi][0]), "=r"(Af[mi][1]), "=r"(Af[mi][2]), "=r"(Af[mi][3])
                    : "r"(addr));
            }
            uint32_t Bf[4][2];
            #pragma unroll
            for (int ni = 0; ni < 4; ni++) {
                const __half* p = &Bs[buf][wn * 32 + ni * 8 + (lane >> 2)]
                                        [kk * 16 + (lane & 3) * 2];
                Bf[ni][0] = *(const uint32_t*)p;        // k, k+1
                Bf[ni][1] = *(const uint32_t*)(p + 8);  // k+8, k+9
            }
            #pragma unroll
            for (int mi = 0; mi < 4; mi++)
                #pragma unroll
                for (int ni = 0; ni < 4; ni++)
                    asm volatile(
                        "mma.sync.aligned.m16n8k16.row.col.f32.f16.f16.f32 "
                        "{%0,%1,%2,%3}, {%4,%5,%6,%7}, {%8,%9}, {%0,%1,%2,%3};"
                        : "+f"(acc[mi][ni][0]), "+f"(acc[mi][ni][1]),
                          "+f"(acc[mi][ni][2]), "+f"(acc[mi][ni][3])
                        : "r"(Af[mi][0]), "r"(Af[mi][1]), "r"(Af[mi][2]), "r"(Af[mi][3]),
                          "r"(Bf[ni][0]), "r"(Bf[ni][1]));
        }
    };

    // ---- prologue: tile 0 ----
    load_gmem(0);
    store_tile(0);
    __syncthreads();

    // ---- mainloop: double-buffered ----
    #pragma unroll 1
    for (int kt = 0; kt < KT; kt++) {
        const int buf = kt & 1;
        if (kt + 1 < KT) load_gmem(kt + 1);
        compute(buf);
        if (kt + 1 < KT) {
            store_tile(buf ^ 1);
            __syncthreads();
        }
    }

    // ---- epilogue: y = fp16_round(acc * scale[n] + bias[n]), f32 out ----
    #pragma unroll
    for (int ni = 0; ni < 4; ni++) {
        const int col = n_base + wn * 32 + ni * 8 + (lane & 3) * 2;
        const float2 s2 = *(const float2*)&scale[col];
        const float2 b2 = *(const float2*)&bias[col];
        #pragma unroll
        for (int mi = 0; mi < 4; mi++) {
            const int row = m_base + wm * 64 + mi * 16 + (lane >> 2);
            float2 o0, o1;
            o0.x = __half2float(__float2half_rn(acc[mi][ni][0] * s2.x + b2.x));
            o0.y = __half2float(__float2half_rn(acc[mi][ni][1] * s2.y + b2.y));
            o1.x = __half2float(__float2half_rn(acc[mi][ni][2] * s2.x + b2.x));
            o1.y = __half2float(__float2half_rn(acc[mi][ni][3] * s2.y + b2.y));
            *(float2*)&out[(size_t)row * N_DIM + col]       = o0;
            *(float2*)&out[(size_t)(row + 8) * N_DIM + col] = o1;
        }
    }
}

extern "C" void kernel_launch(void* const* d_in, const int* in_sizes, int n_in,
                              void* d_out, int out_size)
{
    // Identify inputs by element count:
    // x = 33554432 (f32), qweight = 45088768 (int32), scale/bias = 11008 (f32).
    // scale sits at index 2 under BOTH dict order {x,q,s,b} and alpha order
    // {b,q,s,x}; bias is the other 11008-sized input.
    const float* x = nullptr;
    const int*   qw = nullptr;
    const float* scale = nullptr;
    const float* bias = nullptr;
    for (int i = 0; i < n_in; i++) {
        if (in_sizes[i] == 33554432)      x  = (const float*)d_in[i];
        else if (in_sizes[i] == 45088768) qw = (const int*)d_in[i];
        else if (in_sizes[i] == 11008) {
            if (i == 2) scale = (const float*)d_in[i];
        }
    }
    for (int i = 0; i < n_in; i++) {
        if (in_sizes[i] == 11008 && (const float*)d_in[i] != scale)
            bias = (const float*)d_in[i];
    }
    if (!scale) { scale = bias; }  // degenerate fallback (shouldn't happen)
    float* out = (float*)d_out;

    dim3 grid(N_DIM / BN, M_DIM / BM);   // (86, 64)
    w8_gemm_kernel<<<grid, 256>>>(x, qw, scale, bias, out);
}

// round 12
// speedup vs baseline: 1.4119x; 1.4119x over previous
#include <cuda_runtime.h>
#include <cuda_fp16.h>
#include <cstdint>

// ---------------- problem dims ----------------
constexpr int M_DIM = 8192;    // B*S
constexpr int N_DIM = 11008;   // OUT_F
constexpr int K_DIM = 4096;    // IN_F

// ---------------- tiling ----------------
constexpr int BM = 128;
constexpr int BN = 256;
constexpr int BK = 32;               // fp16 k per stage
constexpr int KT = K_DIM / BK;       // 128 stages
constexpr int STAGES = 4;
constexpr int THREADS = 256;         // 8 warps, 2x4 of 64x64 tiles

// smem: rows of 32 halves + 8 pad = 40 halves = 80B (conflict-free ldmatrix)
constexpr int ROWB = 80;
constexpr int A_STAGE = BM * ROWB;               // 10240
constexpr int B_STAGE = BN * ROWB;               // 20480
constexpr int STAGE   = A_STAGE + B_STAGE;       // 30720
constexpr int SMEM_TOTAL = STAGES * STAGE;       // 122880

// ---------------- scratch globals (allowed) ----------------
__device__ __half g_xh[(size_t)M_DIM * K_DIM];   // 67 MB
__device__ __half g_wh[(size_t)N_DIM * K_DIM];   // 90 MB

__device__ __forceinline__ uint32_t smem_u32(const void* p) {
    uint32_t a;
    asm("{ .reg .u64 t; cvta.to.shared.u64 t, %1; cvt.u32.u64 %0, t; }"
        : "=r"(a) : "l"(p));
    return a;
}
__device__ __forceinline__ void cp16(uint32_t saddr, const void* g) {
    asm volatile("cp.async.cg.shared.global [%0], [%1], 16;" :: "r"(saddr), "l"(g));
}

// ---------------- conversion prepass ----------------
__global__ void conv_x_kernel(const float* __restrict__ x) {
    size_t i = (size_t)blockIdx.x * blockDim.x + threadIdx.x;   // over M*K/4
    float4 v = reinterpret_cast<const float4*>(x)[i];
    __half2 h0 = __floats2half2_rn(v.x, v.y);
    __half2 h1 = __floats2half2_rn(v.z, v.w);
    uint2 u;
    u.x = *reinterpret_cast<uint32_t*>(&h0);
    u.y = *reinterpret_cast<uint32_t*>(&h1);
    reinterpret_cast<uint2*>(g_xh)[i] = u;
}
__global__ void conv_w_kernel(const int* __restrict__ qw) {
    size_t i = (size_t)blockIdx.x * blockDim.x + threadIdx.x;   // over N*K/4
    int4 v = reinterpret_cast<const int4*>(qw)[i];
    __half2 h0 = __halves2half2(__short2half_rn((short)v.x), __short2half_rn((short)v.y));
    __half2 h1 = __halves2half2(__short2half_rn((short)v.z), __short2half_rn((short)v.w));
    uint2 u;
    u.x = *reinterpret_cast<uint32_t*>(&h0);
    u.y = *reinterpret_cast<uint32_t*>(&h1);
    reinterpret_cast<uint2*>(g_wh)[i] = u;
}

// ---------------- GEMM ----------------
__global__ void __launch_bounds__(THREADS, 1)
w8_gemm_kernel(const float* __restrict__ scale,
               const float* __restrict__ bias,
               float* __restrict__ out)
{
    extern __shared__ __align__(128) char smem[];
    const uint32_t sbase = smem_u32(smem);

    const int tid  = threadIdx.x;
    const int lane = tid & 31;
    const int wid  = tid >> 5;
    const int wm   = wid >> 2;   // 0..1 (64 M each)
    const int wn   = wid & 3;    // 0..3 (64 N each)

    const int m_base = blockIdx.y * BM;
    const int n_base = blockIdx.x * BN;

    // ---- cp.async source/dest mapping ----
    // A: 512 chunks of 16B (128 rows x 4), thread does 2
    // B: 1024 chunks      (256 rows x 4), thread does 4
    uint32_t a_soff[2]; const __half* a_g[2];
    #pragma unroll
    for (int i = 0; i < 2; i++) {
        int c = tid + i * 256, row = c >> 2, col = c & 3;
        a_soff[i] = (uint32_t)(row * ROWB + col * 16);
        a_g[i] = g_xh + (size_t)(m_base + row) * K_DIM + col * 8;
    }
    uint32_t b_soff[4]; const __half* b_g[4];
    #pragma unroll
    for (int j = 0; j < 4; j++) {
        int c = tid + j * 256, row = c >> 2, col = c & 3;
        b_soff[j] = (uint32_t)(A_STAGE + row * ROWB + col * 16);
        b_g[j] = g_wh + (size_t)(n_base + row) * K_DIM + col * 8;
    }

    auto issue_stage = [&](int kt, int buf) {
        const uint32_t s0 = sbase + buf * STAGE;
        #pragma unroll
        for (int i = 0; i < 2; i++) cp16(s0 + a_soff[i], a_g[i] + kt * BK);
        #pragma unroll
        for (int j = 0; j < 4; j++) cp16(s0 + b_soff[j], b_g[j] + kt * BK);
        asm volatile("cp.async.commit_group;");
    };

    // ---- ldmatrix addresses (per-warp constants) ----
    // A (x4, non-trans): matrices = (rows0-7,k0)(rows8-15,k0)(rows0-7,k8)(rows8-15,k8)
    const uint32_t a_ld_base = sbase
        + (uint32_t)((wm * 64 + (lane & 15)) * ROWB)
        + (uint32_t)((lane >> 4) * 8 * 2);
    // B (x4, NON-trans; B smem is [n][k] so rows are n, pairs along k):
    // matrix m = lane>>3: n_off = (m>>1)*8, k_off = (m&1)*8
    const uint32_t b_ld_base = sbase + A_STAGE
        + (uint32_t)((wn * 64 + ((lane >> 4) & 1) * 8 + (lane & 7)) * ROWB)
        + (uint32_t)((((lane >> 3) & 1) * 8) * 2);

    float acc[4][8][4];
    #pragma unroll
    for (int mi = 0; mi < 4; mi++)
        #pragma unroll
        for (int ni = 0; ni < 8; ni++)
            #pragma unroll
            for (int e = 0; e < 4; e++) acc[mi][ni][e] = 0.f;

    // ---- prologue: issue stages 0..2 ----
    issue_stage(0, 0);
    issue_stage(1, 1);
    issue_stage(2, 2);

    // ---- mainloop ----
    #pragma unroll 1
    for (int kt = 0; kt < KT; kt++) {
        if (kt < KT - 2)       asm volatile("cp.async.wait_group 2;");
        else if (kt == KT - 2) asm volatile("cp.async.wait_group 1;");
        else                   asm volatile("cp.async.wait_group 0;");
        __syncthreads();

        const uint32_t sb = (uint32_t)((kt & 3) * STAGE);
        #pragma unroll
        for (int kk = 0; kk < 2; kk++) {
            uint32_t Af[4][4];
            #pragma unroll
            for (int mi = 0; mi < 4; mi++) {
                uint32_t addr = a_ld_base + sb + mi * 16 * ROWB + kk * 32;
                asm volatile(
                    "ldmatrix.sync.aligned.m8n8.x4.shared.b16 {%0,%1,%2,%3}, [%4];"
                    : "=r"(Af[mi][0]), "=r"(Af[mi][1]), "=r"(Af[mi][2]), "=r"(Af[mi][3])
                    : "r"(addr));
            }
            #pragma unroll
            for (int g = 0; g < 4; g++) {
                uint32_t Bf[4];
                uint32_t addr = b_ld_base + sb + g * 16 * ROWB + kk * 32;
                asm volatile(
                    "ldmatrix.sync.aligned.m8n8.x4.shared.b16 {%0,%1,%2,%3}, [%4];"
                    : "=r"(Bf[0]), "=r"(Bf[1]), "=r"(Bf[2]), "=r"(Bf[3])
                    : "r"(addr));
                // Bf[0],Bf[1] = n-subgroup 0 (k0-7, k8-15); Bf[2],Bf[3] = n-subgroup 1
                #pragma unroll
                for (int mi = 0; mi < 4; mi++) {
                    #pragma unroll
                    for (int h = 0; h < 2; h++) {
                        float* a4 = acc[mi][g * 2 + h];
                        asm volatile(
                            "mma.sync.aligned.m16n8k16.row.col.f32.f16.f16.f32 "
                            "{%0,%1,%2,%3}, {%4,%5,%6,%7}, {%8,%9}, {%0,%1,%2,%3};"
                            : "+f"(a4[0]), "+f"(a4[1]), "+f"(a4[2]), "+f"(a4[3])
                            : "r"(Af[mi][0]), "r"(Af[mi][1]), "r"(Af[mi][2]), "r"(Af[mi][3]),
                              "r"(Bf[h * 2]), "r"(Bf[h * 2 + 1]));
                    }
                }
            }
        }
        __syncthreads();
        if (kt + 3 < KT) issue_stage(kt + 3, (kt + 3) & 3);
    }

    // ---- epilogue: y = fp16_round(acc * scale + bias), f32 out ----
    float2 s2[8], b2[8];
    #pragma unroll
    for (int ni = 0; ni < 8; ni++) {
        const int col = n_base + wn * 64 + ni * 8 + (lane & 3) * 2;
        s2[ni] = *(const float2*)&scale[col];
        b2[ni] = *(const float2*)&bias[col];
    }
    #pragma unroll
    for (int mi = 0; mi < 4; mi++) {
        const int row = m_base + wm * 64 + mi * 16 + (lane >> 2);
        #pragma unroll
        for (int ni = 0; ni < 8; ni++) {
            const int col = n_base + wn * 64 + ni * 8 + (lane & 3) * 2;
            float2 o0, o1;
            o0.x = __half2float(__float2half_rn(acc[mi][ni][0] * s2[ni].x + b2[ni].x));
            o0.y = __half2float(__float2half_rn(acc[mi][ni][1] * s2[ni].y + b2[ni].y));
            o1.x = __half2float(__float2half_rn(acc[mi][ni][2] * s2[ni].x + b2[ni].x));
            o1.y = __half2float(__float2half_rn(acc[mi][ni][3] * s2[ni].y + b2[ni].y));
            *(float2*)&out[(size_t)row * N_DIM + col]       = o0;
            *(float2*)&out[(size_t)(row + 8) * N_DIM + col] = o1;
        }
    }
}

// ---------------- launch ----------------
extern "C" void kernel_launch(void* const* d_in, const int* in_sizes, int n_in,
                              void* d_out, int out_size)
{
    // x = 33554432 (f32), qweight = 45088768 (int32), scale/bias = 11008 (f32)
    // scale sits at index 2 under both dict and alphabetical orderings.
    const float* x = nullptr;
    const int*   qw = nullptr;
    const float* scale = nullptr;
    const float* bias = nullptr;
    for (int i = 0; i < n_in; i++) {
        if (in_sizes[i] == 33554432)      x  = (const float*)d_in[i];
        else if (in_sizes[i] == 45088768) qw = (const int*)d_in[i];
        else if (in_sizes[i] == 11008 && i == 2) scale = (const float*)d_in[i];
    }
    for (int i = 0; i < n_in; i++) {
        if (in_sizes[i] == 11008 && (const float*)d_in[i] != scale)
            bias = (const float*)d_in[i];
    }
    if (!scale) scale = bias;
    float* out = (float*)d_out;

    cudaFuncSetAttribute(w8_gemm_kernel,
                         cudaFuncAttributeMaxDynamicSharedMemorySize, SMEM_TOTAL);

    conv_x_kernel<<<(size_t)M_DIM * K_DIM / 4 / 256, 256>>>(x);
    conv_w_kernel<<<(size_t)N_DIM * K_DIM / 4 / 256, 256>>>(qw);

    dim3 grid(N_DIM / BN, M_DIM / BM);   // (43, 64)
    w8_gemm_kernel<<<grid, THREADS, SMEM_TOTAL>>>(scale, bias, out);
}

// round 15
// speedup vs baseline: 1.6535x; 1.1711x over previous
#include <cuda_runtime.h>
#include <cuda_fp16.h>
#include <cstdint>

// ---------------- problem dims ----------------
constexpr int M_DIM = 8192;    // B*S
constexpr int N_DIM = 11008;   // OUT_F
constexpr int K_DIM = 4096;    // IN_F

// ---------------- tiling ----------------
constexpr int BM = 128;
constexpr int BN = 256;
constexpr int BK = 64;               // fp16 k per stage
constexpr int KT = K_DIM / BK;       // 64 stages
constexpr int STAGES = 3;
constexpr int THREADS = 256;         // 8 warps, 2x4 of 64x64 tiles

// smem rows: 64 halves + 8 pad = 72 halves = 144B
// bank stride 36 words -> 8 consecutive rows hit banks 4i mod 32: distinct
constexpr int ROWB = 144;
constexpr int A_STAGE = BM * ROWB;               // 18432
constexpr int B_STAGE = BN * ROWB;               // 36864
constexpr int STAGE   = A_STAGE + B_STAGE;       // 55296
constexpr int SMEM_TOTAL = STAGES * STAGE;       // 165888

// ---------------- scratch globals (allowed) ----------------
__device__ __half g_xh[(size_t)M_DIM * K_DIM];   // 67 MB
__device__ __half g_wh[(size_t)N_DIM * K_DIM];   // 90 MB

__device__ __forceinline__ uint32_t smem_u32(const void* p) {
    uint32_t a;
    asm("{ .reg .u64 t; cvta.to.shared.u64 t, %1; cvt.u32.u64 %0, t; }"
        : "=r"(a) : "l"(p));
    return a;
}
__device__ __forceinline__ void cp16(uint32_t saddr, const void* g) {
    asm volatile("cp.async.cg.shared.global [%0], [%1], 16;" :: "r"(saddr), "l"(g));
}

// ---------------- conversion prepass ----------------
__global__ void conv_x_kernel(const float* __restrict__ x) {
    size_t i = (size_t)blockIdx.x * blockDim.x + threadIdx.x;   // over M*K/4
    float4 v = reinterpret_cast<const float4*>(x)[i];
    __half2 h0 = __floats2half2_rn(v.x, v.y);
    __half2 h1 = __floats2half2_rn(v.z, v.w);
    uint2 u;
    u.x = *reinterpret_cast<uint32_t*>(&h0);
    u.y = *reinterpret_cast<uint32_t*>(&h1);
    reinterpret_cast<uint2*>(g_xh)[i] = u;
}
__global__ void conv_w_kernel(const int* __restrict__ qw) {
    size_t i = (size_t)blockIdx.x * blockDim.x + threadIdx.x;   // over N*K/4
    int4 v = reinterpret_cast<const int4*>(qw)[i];
    __half2 h0 = __halves2half2(__short2half_rn((short)v.x), __short2half_rn((short)v.y));
    __half2 h1 = __halves2half2(__short2half_rn((short)v.z), __short2half_rn((short)v.w));
    uint2 u;
    u.x = *reinterpret_cast<uint32_t*>(&h0);
    u.y = *reinterpret_cast<uint32_t*>(&h1);
    reinterpret_cast<uint2*>(g_wh)[i] = u;
}

// ---------------- GEMM ----------------
__global__ void __launch_bounds__(THREADS, 1)
w8_gemm_kernel(const float* __restrict__ scale,
               const float* __restrict__ bias,
               float* __restrict__ out)
{
    extern __shared__ __align__(128) char smem[];
    const uint32_t sbase = smem_u32(smem);

    const int tid  = threadIdx.x;
    const int lane = tid & 31;
    const int wid  = tid >> 5;
    const int wm   = wid >> 2;   // 0..1 (64 M each)
    const int wn   = wid & 3;    // 0..3 (64 N each)

    const int m_base = blockIdx.y * BM;
    const int n_base = blockIdx.x * BN;

    // ---- cp.async mapping: BK=64 -> 8 x 16B chunks per row ----
    // A: 1024 chunks (128 rows x 8), thread does 4
    // B: 2048 chunks (256 rows x 8), thread does 8
    uint32_t a_soff[4]; const __half* a_g[4];
    #pragma unroll
    for (int i = 0; i < 4; i++) {
        int c = tid + i * 256, row = c >> 3, col = c & 7;
        a_soff[i] = (uint32_t)(row * ROWB + col * 16);
        a_g[i] = g_xh + (size_t)(m_base + row) * K_DIM + col * 8;
    }
    uint32_t b_soff[8]; const __half* b_g[8];
    #pragma unroll
    for (int j = 0; j < 8; j++) {
        int c = tid + j * 256, row = c >> 3, col = c & 7;
        b_soff[j] = (uint32_t)(A_STAGE + row * ROWB + col * 16);
        b_g[j] = g_wh + (size_t)(n_base + row) * K_DIM + col * 8;
    }

    auto issue_stage = [&](int kt, int buf) {
        const uint32_t s0 = sbase + buf * STAGE;
        #pragma unroll
        for (int i = 0; i < 4; i++) cp16(s0 + a_soff[i], a_g[i] + kt * BK);
        #pragma unroll
        for (int j = 0; j < 8; j++) cp16(s0 + b_soff[j], b_g[j] + kt * BK);
        asm volatile("cp.async.commit_group;");
    };

    // ---- ldmatrix addresses (per-warp constants) ----
    // A (x4, non-trans): matrices = (rows0-7,k0)(rows8-15,k0)(rows0-7,k8)(rows8-15,k8)
    const uint32_t a_ld_base = sbase
        + (uint32_t)((wm * 64 + (lane & 15)) * ROWB)
        + (uint32_t)((lane >> 4) * 8 * 2);
    // B (x4, non-trans; smem [n][k]): matrix m=lane>>3: n_off=(m>>1)*8, k_off=(m&1)*8
    const uint32_t b_ld_base = sbase + A_STAGE
        + (uint32_t)((wn * 64 + ((lane >> 4) & 1) * 8 + (lane & 7)) * ROWB)
        + (uint32_t)((((lane >> 3) & 1) * 8) * 2);

    float acc[4][8][4];
    #pragma unroll
    for (int mi = 0; mi < 4; mi++)
        #pragma unroll
        for (int ni = 0; ni < 8; ni++)
            #pragma unroll
            for (int e = 0; e < 4; e++) acc[mi][ni][e] = 0.f;

    // ---- prologue: issue stages 0..1 ----
    issue_stage(0, 0);
    issue_stage(1, 1);

    // ---- mainloop: ONE barrier per iteration ----
    #pragma unroll 1
    for (int kt = 0; kt < KT; kt++) {
        if (kt == KT - 1) asm volatile("cp.async.wait_group 0;");
        else              asm volatile("cp.async.wait_group 1;");
        __syncthreads();
        // prefetch into the buffer consumed in iteration kt-1 (all warps done with it)
        if (kt + 2 < KT) {
            int nb = (kt + 2) % 3;
            issue_stage(kt + 2, nb);
        }

        const uint32_t sb = (uint32_t)((kt % 3) * STAGE);
        #pragma unroll
        for (int kk = 0; kk < 4; kk++) {
            uint32_t Af[4][4];
            #pragma unroll
            for (int mi = 0; mi < 4; mi++) {
                uint32_t addr = a_ld_base + sb + mi * 16 * ROWB + kk * 32;
                asm volatile(
                    "ldmatrix.sync.aligned.m8n8.x4.shared.b16 {%0,%1,%2,%3}, [%4];"
                    : "=r"(Af[mi][0]), "=r"(Af[mi][1]), "=r"(Af[mi][2]), "=r"(Af[mi][3])
                    : "r"(addr));
            }
            #pragma unroll
            for (int g = 0; g < 4; g++) {
                uint32_t Bf[4];
                uint32_t addr = b_ld_base + sb + g * 16 * ROWB + kk * 32;
                asm volatile(
                    "ldmatrix.sync.aligned.m8n8.x4.shared.b16 {%0,%1,%2,%3}, [%4];"
                    : "=r"(Bf[0]), "=r"(Bf[1]), "=r"(Bf[2]), "=r"(Bf[3])
                    : "r"(addr));
                #pragma unroll
                for (int mi = 0; mi < 4; mi++) {
                    #pragma unroll
                    for (int h = 0; h < 2; h++) {
                        float* a4 = acc[mi][g * 2 + h];
                        asm volatile(
                            "mma.sync.aligned.m16n8k16.row.col.f32.f16.f16.f32 "
                            "{%0,%1,%2,%3}, {%4,%5,%6,%7}, {%8,%9}, {%0,%1,%2,%3};"
                            : "+f"(a4[0]), "+f"(a4[1]), "+f"(a4[2]), "+f"(a4[3])
                            : "r"(Af[mi][0]), "r"(Af[mi][1]), "r"(Af[mi][2]), "r"(Af[mi][3]),
                              "r"(Bf[h * 2]), "r"(Bf[h * 2 + 1]));
                    }
                }
            }
        }
    }

    // ---- epilogue: y = fp16_round(acc * scale + bias), f32 out ----
    float2 s2[8], b2[8];
    #pragma unroll
    for (int ni = 0; ni < 8; ni++) {
        const int col = n_base + wn * 64 + ni * 8 + (lane & 3) * 2;
        s2[ni] = *(const float2*)&scale[col];
        b2[ni] = *(const float2*)&bias[col];
    }
    #pragma unroll
    for (int mi = 0; mi < 4; mi++) {
        const int row = m_base + wm * 64 + mi * 16 + (lane >> 2);
        #pragma unroll
        for (int ni = 0; ni < 8; ni++) {
            const int col = n_base + wn * 64 + ni * 8 + (lane & 3) * 2;
            float2 o0, o1;
            o0.x = __half2float(__float2half_rn(acc[mi][ni][0] * s2[ni].x + b2[ni].x));
            o0.y = __half2float(__float2half_rn(acc[mi][ni][1] * s2[ni].y + b2[ni].y));
            o1.x = __half2float(__float2half_rn(acc[mi][ni][2] * s2[ni].x + b2[ni].x));
            o1.y = __half2float(__float2half_rn(acc[mi][ni][3] * s2[ni].y + b2[ni].y));
            *(float2*)&out[(size_t)row * N_DIM + col]       = o0;
            *(float2*)&out[(size_t)(row + 8) * N_DIM + col] = o1;
        }
    }
}

// ---------------- launch ----------------
extern "C" void kernel_launch(void* const* d_in, const int* in_sizes, int n_in,
                              void* d_out, int out_size)
{
    // x = 33554432 (f32), qweight = 45088768 (int32), scale/bias = 11008 (f32)
    const float* x = nullptr;
    const int*   qw = nullptr;
    const float* scale = nullptr;
    const float* bias = nullptr;
    for (int i = 0; i < n_in; i++) {
        if (in_sizes[i] == 33554432)      x  = (const float*)d_in[i];
        else if (in_sizes[i] == 45088768) qw = (const int*)d_in[i];
        else if (in_sizes[i] == 11008 && i == 2) scale = (const float*)d_in[i];
    }
    for (int i = 0; i < n_in; i++) {
        if (in_sizes[i] == 11008 && (const float*)d_in[i] != scale)
            bias = (const float*)d_in[i];
    }
    if (!scale) scale = bias;
    float* out = (float*)d_out;

    cudaFuncSetAttribute(w8_gemm_kernel,
                         cudaFuncAttributeMaxDynamicSharedMemorySize, SMEM_TOTAL);

    conv_x_kernel<<<(size_t)M_DIM * K_DIM / 4 / 256, 256>>>(x);
    conv_w_kernel<<<(size_t)N_DIM * K_DIM / 4 / 256, 256>>>(qw);

    dim3 grid(N_DIM / BN, M_DIM / BM);   // (43, 64)
    w8_gemm_kernel<<<grid, THREADS, SMEM_TOTAL>>>(scale, bias, out);
}